// round 6
// baseline (speedup 1.0000x reference)
#include <cuda_runtime.h>
#include <cuda_bf16.h>
#include <stdint.h>

#define QN 32
#define DN 4096
#define DIMN 384
#define N2 192
#define QD (QN*DN)
#define KC 192          // K chunk
#define AW 100          // h1/doc smem row stride in words (192 bf16 = 96 w + 4 pad)
#define BW 196          // W smem row stride in words (384 bf16 = 192 w + 4 pad)

static __device__ __align__(16) float         g_A32[QN*DIMN];
static __device__ __align__(16) float         g_dense[QD];
static __device__ __align__(16) __nv_bfloat16 g_Bd[DN*DIMN];
static __device__ __align__(16) __nv_bfloat16 g_W2T[N2*DIMN];     // [n][k]
static __device__ __align__(16) __nv_bfloat16 g_W1dT[DIMN*DIMN];  // [n][k]

__device__ __forceinline__ void mma16816(float* c, const uint32_t* a, const uint32_t* b){
    asm volatile(
        "mma.sync.aligned.m16n8k16.row.col.f32.bf16.bf16.f32 "
        "{%0,%1,%2,%3}, {%4,%5,%6,%7}, {%8,%9}, {%0,%1,%2,%3};"
        : "+f"(c[0]), "+f"(c[1]), "+f"(c[2]), "+f"(c[3])
        : "r"(a[0]), "r"(a[1]), "r"(a[2]), "r"(a[3]), "r"(b[0]), "r"(b[1]));
}
__device__ __forceinline__ uint32_t packbf(float x, float y){
    __nv_bfloat162 h = __floats2bfloat162_rn(x, y);
    return *(uint32_t*)&h;
}

// ---- prep: transpose+convert weights -------------------------------------
__global__ __launch_bounds__(256) void hr_prep_w(
    const float* __restrict__ W1, const float* __restrict__ W2)
{
    int i = blockIdx.x * 256 + threadIdx.x;
    if (i < N2 * DIMN) {
        int n = i / DIMN, k = i - n * DIMN;
        g_W2T[i] = __float2bfloat16(W2[k * N2 + n]);
        return;
    }
    i -= N2 * DIMN;
    if (i < DIMN * DIMN) {
        int n = i / DIMN, k = i - n * DIMN;
        g_W1dT[i] = __float2bfloat16(W1[(DIMN + k) * DIMN + n]);
    }
}

// ---- prep: A32 = query @ W1q + b1 (fp32) ---------------------------------
__global__ __launch_bounds__(256) void hr_prep_a32(
    const float* __restrict__ qd, const float* __restrict__ W1, const float* __restrict__ b1)
{
    int idx = blockIdx.x * 256 + threadIdx.x;
    if (idx >= QN * DIMN) return;
    int qi = idx / DIMN, n = idx - qi * DIMN;
    float s = b1[n];
#pragma unroll 4
    for (int k = 0; k < DIMN; k++) s = fmaf(qd[qi * DIMN + k], W1[k * DIMN + n], s);
    g_A32[idx] = s;
}

// ---- prep: dense = query @ doc^T (fp32) ----------------------------------
__global__ __launch_bounds__(256) void hr_prep_dense(
    const float* __restrict__ qd, const float* __restrict__ doc)
{
    __shared__ float q_sh[QN * DIMN];
    int tid = threadIdx.x;
    for (int i = tid; i < QN * DIMN; i += 256) q_sh[i] = qd[i];
    __syncthreads();
    int w = tid >> 5, lane = tid & 31;
    int d = blockIdx.x * 8 + w;
    float dr[12];
#pragma unroll
    for (int i = 0; i < 12; i++) dr[i] = doc[(size_t)d * DIMN + lane + 32 * i];
    for (int qi = 0; qi < QN; qi++) {
        float s = 0.f;
#pragma unroll
        for (int i = 0; i < 12; i++) s = fmaf(dr[i], q_sh[qi * DIMN + lane + 32 * i], s);
#pragma unroll
        for (int o = 16; o; o >>= 1) s += __shfl_xor_sync(0xffffffffu, s, o);
        if (lane == 0) g_dense[qi * DN + d] = s;
    }
}

// ---- K1: Bd = doc @ W1d, HMMA, out bf16 ----------------------------------
__global__ __launch_bounds__(256, 1) void hr_k1(const float* __restrict__ doc)
{
    extern __shared__ uint32_t smw[];
    uint32_t* Wsm = smw;                 // [192][BW]
    uint32_t* Asm = smw + N2 * BW;       // [128][AW]
    const int tid = threadIdx.x, lane = tid & 31, wid = tid >> 5;
    const int wm = wid & 1, wn = wid >> 1;
    const int dt = blockIdx.x >> 1, nh = blockIdx.x & 1, d0 = dt << 7;

    for (int i = tid; i < N2 * (DIMN / 2); i += 256) {
        int n = i / (DIMN / 2), kw = i - n * (DIMN / 2);
        Wsm[n * BW + kw] = ((const uint32_t*)g_W1dT)[(size_t)(nh * N2 + n) * (DIMN / 2) + kw];
    }
    float acc[4][6][4];
#pragma unroll
    for (int a = 0; a < 4; a++)
#pragma unroll
        for (int b = 0; b < 6; b++)
#pragma unroll
            for (int c = 0; c < 4; c++) acc[a][b][c] = 0.f;

    for (int ch = 0; ch < 2; ch++) {
        __syncthreads();
        for (int i = tid; i < 128 * (KC / 2); i += 256) {
            int r = i / (KC / 2), c = i - r * (KC / 2);
            int k = ch * KC + 2 * c;
            float2 dv = *(const float2*)&doc[(size_t)(d0 + r) * DIMN + k];
            Asm[r * AW + c] = packbf(dv.x, dv.y);
        }
        __syncthreads();
#pragma unroll
        for (int ks = 0; ks < KC / 16; ks++) {
            int kw = ch * (KC / 2) + ks * 8;
            int kwa = ks * 8;
            uint32_t a[4][4], bf[6][2];
#pragma unroll
            for (int im = 0; im < 4; im++) {
                const uint32_t* p = Asm + (wm * 64 + im * 16 + (lane >> 2)) * AW + kwa + (lane & 3);
                a[im][0] = p[0]; a[im][1] = p[8 * AW]; a[im][2] = p[4]; a[im][3] = p[8 * AW + 4];
            }
#pragma unroll
            for (int jn = 0; jn < 6; jn++) {
                const uint32_t* p = Wsm + (wn * 48 + jn * 8 + (lane >> 2)) * BW + kw + (lane & 3);
                bf[jn][0] = p[0]; bf[jn][1] = p[4];
            }
#pragma unroll
            for (int im = 0; im < 4; im++)
#pragma unroll
                for (int jn = 0; jn < 6; jn++) mma16816(acc[im][jn], a[im], bf[jn]);
        }
    }
    // write Bd bf16
#pragma unroll
    for (int im = 0; im < 4; im++)
#pragma unroll
        for (int hf = 0; hf < 2; hf++) {
            int m = wm * 64 + im * 16 + hf * 8 + (lane >> 2);
            int d = d0 + m;
#pragma unroll
            for (int jn = 0; jn < 6; jn++) {
                int n = nh * N2 + wn * 48 + jn * 8 + (lane & 3) * 2;
                ((uint32_t*)g_Bd)[(size_t)d * (DIMN / 2) + (n >> 1)] =
                    packbf(acc[im][jn][hf * 2], acc[im][jn][hf * 2 + 1]);
            }
        }
}

// ---- K2: fused h1 + layer2 HMMA + epilogue, persistent -------------------
__global__ __launch_bounds__(256, 1) void hr_k2(
    const float* __restrict__ sparse, const float* __restrict__ W1,
    const float* __restrict__ b2, const float* __restrict__ W3,
    const float* __restrict__ b3, float* __restrict__ out, int out_size)
{
    extern __shared__ uint32_t smw[];
    uint32_t* Wsm = smw;                 // [192][BW]
    uint32_t* Asm = smw + N2 * BW;       // [128][AW]
    float* b2s = (float*)(Asm + 128 * AW);
    float* w3s = b2s + N2;
    float* a_s = w3s + N2;
    float* u_s = a_s + DIMN;
    float* v_s = u_s + DIMN;
    float* dns = v_s + DIMN;
    float* sps = dns + 128;
    float* zbuf = sps + 128;
    const int tid = threadIdx.x, lane = tid & 31, wid = tid >> 5;
    const int wm = wid & 1, wn = wid >> 1;

    for (int i = tid; i < N2 * (DIMN / 2); i += 256) {
        int n = i / (DIMN / 2), kw = i - n * (DIMN / 2);
        Wsm[n * BW + kw] = ((const uint32_t*)g_W2T)[(size_t)n * (DIMN / 2) + kw];
    }
    for (int i = tid; i < N2; i += 256) { b2s[i] = b2[i]; w3s[i] = W3[i]; }
    for (int i = tid; i < DIMN; i += 256) {
        u_s[i] = W1[768 * DIMN + i];
        v_s[i] = W1[769 * DIMN + i];
    }

    for (int u = blockIdx.x; u < QN * 32; u += gridDim.x) {
        int q = u >> 5, dt = u & 31, d0 = dt << 7;
        __syncthreads();   // prev epilogue done with zbuf/a_s/dns/sps
        for (int i = tid; i < DIMN; i += 256) a_s[i] = g_A32[q * DIMN + i];
        if (tid < 128) {
            dns[tid] = g_dense[q * DN + d0 + tid];
            sps[tid] = sparse[q * DN + d0 + tid];
            zbuf[tid] = 0.f;
        }
        float acc[4][6][4];
#pragma unroll
        for (int a = 0; a < 4; a++)
#pragma unroll
            for (int b = 0; b < 6; b++)
#pragma unroll
                for (int c = 0; c < 4; c++) acc[a][b][c] = 0.f;

        for (int ch = 0; ch < 2; ch++) {
            __syncthreads();   // unit loads visible / prev mma done with Asm
            for (int i = tid; i < 128 * (KC / 2); i += 256) {
                int r = i / (KC / 2), c = i - r * (KC / 2);
                int k = ch * KC + 2 * c;
                uint32_t bdw = ((const uint32_t*)g_Bd)[(size_t)(d0 + r) * (DIMN / 2) + (k >> 1)];
                float2 bv = __bfloat1622float2(*(__nv_bfloat162*)&bdw);
                float dsc = dns[r], ssc = sps[r];
                float x0 = a_s[k]     + bv.x + dsc * u_s[k]     + ssc * v_s[k];
                float x1 = a_s[k + 1] + bv.y + dsc * u_s[k + 1] + ssc * v_s[k + 1];
                Asm[r * AW + c] = packbf(fmaxf(x0, 0.f), fmaxf(x1, 0.f));
            }
            __syncthreads();
#pragma unroll
            for (int ks = 0; ks < KC / 16; ks++) {
                int kw = ch * (KC / 2) + ks * 8;
                int kwa = ks * 8;
                uint32_t a[4][4], bf[6][2];
#pragma unroll
                for (int im = 0; im < 4; im++) {
                    const uint32_t* p = Asm + (wm * 64 + im * 16 + (lane >> 2)) * AW + kwa + (lane & 3);
                    a[im][0] = p[0]; a[im][1] = p[8 * AW]; a[im][2] = p[4]; a[im][3] = p[8 * AW + 4];
                }
#pragma unroll
                for (int jn = 0; jn < 6; jn++) {
                    const uint32_t* p = Wsm + (wn * 48 + jn * 8 + (lane >> 2)) * BW + kw + (lane & 3);
                    bf[jn][0] = p[0]; bf[jn][1] = p[4];
                }
#pragma unroll
                for (int im = 0; im < 4; im++)
#pragma unroll
                    for (int jn = 0; jn < 6; jn++) mma16816(acc[im][jn], a[im], bf[jn]);
            }
        }
        // epilogue: z[m] = sum_n relu(D+b2)*W3
#pragma unroll
        for (int im = 0; im < 4; im++)
#pragma unroll
            for (int hf = 0; hf < 2; hf++) {
                int m = wm * 64 + im * 16 + hf * 8 + (lane >> 2);
                float val = 0.f;
#pragma unroll
                for (int jn = 0; jn < 6; jn++) {
                    int n = wn * 48 + jn * 8 + (lane & 3) * 2;
                    val += fmaxf(acc[im][jn][hf * 2]     + b2s[n],     0.f) * w3s[n];
                    val += fmaxf(acc[im][jn][hf * 2 + 1] + b2s[n + 1], 0.f) * w3s[n + 1];
                }
                val += __shfl_xor_sync(0xffffffffu, val, 1);
                val += __shfl_xor_sync(0xffffffffu, val, 2);
                if ((lane & 3) == 0) atomicAdd(&zbuf[m], val);
            }
        __syncthreads();
        if (tid < 128) {
            float z = zbuf[tid] + b3[0];
            float w = 1.f / (1.f + expf(-z));
            float dn = dns[tid], sp = sps[tid];
            float fin = w * dn + (1.f - w) * sp;
            int o = q * DN + d0 + tid;
            if (o < out_size)          out[o] = fin;
            if (QD + o < out_size)     out[QD + o] = dn;
            if (2 * QD + o < out_size) out[2 * QD + o] = sp;
        }
    }
}

extern "C" void kernel_launch(void* const* d_in, const int* in_sizes, int n_in,
                              void* d_out, int out_size)
{
    const float* qd     = (const float*)d_in[0];
    const float* doc    = (const float*)d_in[1];
    const float* sparse = (const float*)d_in[2];
    const float* W1     = (const float*)d_in[3];
    const float* b1     = (const float*)d_in[4];
    const float* W2     = (const float*)d_in[5];
    const float* b2     = (const float*)d_in[6];
    const float* W3     = (const float*)d_in[7];
    const float* b3     = (const float*)d_in[8];
    float* out = (float*)d_out;

    const int SMEM_K1 = (N2 * BW + 128 * AW) * 4;                 // 201728
    const int SMEM_K2 = SMEM_K1 + (2 * N2 + 3 * DIMN + 3 * 128) * 4; // +7680
    cudaFuncSetAttribute(hr_k1, cudaFuncAttributeMaxDynamicSharedMemorySize, SMEM_K1);
    cudaFuncSetAttribute(hr_k2, cudaFuncAttributeMaxDynamicSharedMemorySize, SMEM_K2);

    int wtot = N2 * DIMN + DIMN * DIMN;
    hr_prep_w<<<(wtot + 255) / 256, 256>>>(W1, W2);
    hr_prep_a32<<<(QN * DIMN + 255) / 256, 256>>>(qd, W1, b1);
    hr_prep_dense<<<DN / 8, 256>>>(qd, doc);
    hr_k1<<<64, 256, SMEM_K1>>>(doc);
    hr_k2<<<148, 256, SMEM_K2>>>(sparse, W1, b2, W3, b3, out, out_size);
}